// round 15
// baseline (speedup 1.0000x reference)
#include <cuda_runtime.h>
#include <cuda_bf16.h>
#include <cstdint>
#include <cstddef>

#define PB 4
#define PC 512
#define PCK 64
#define PN 4096

typedef __nv_bfloat16 bf16;

// ---------------- static scratch ----------------
__device__ bf16     g_xT[(size_t)PB * PN * PC];     // [b][n][c]
__device__ bf16     g_Wkb[PCK * PC];
__device__ bf16     g_Wvb[PC * PC];
__device__ bf16     g_qkt[(size_t)PB * PN * PCK];   // [b][n][ck]
__device__ bf16     g_v[(size_t)PB * PC * PN];      // [b][c][m]
__device__ bf16     g_E[(size_t)PB * PN * PN];      // [b][n][m]
__device__ float    g_qn[PB * PN];
__device__ unsigned g_mbits[PB];
__device__ float    g_lp[(size_t)PB * 32 * PN];

// ---------------- helpers ----------------
static __device__ __forceinline__ uint32_t s2u(const void* p) {
    uint32_t a;
    asm("{ .reg .u64 t; cvta.to.shared.u64 t, %1; cvt.u32.u64 %0, t; }" : "=r"(a) : "l"(p));
    return a;
}
static __device__ __forceinline__ void cp16(uint32_t dst, const void* src) {
    asm volatile("cp.async.cg.shared.global [%0], [%1], 16;" :: "r"(dst), "l"(src));
}
static __device__ __forceinline__ void ldm4(uint32_t a, uint32_t* r) {
    asm volatile("ldmatrix.sync.aligned.m8n8.x4.shared.b16 {%0,%1,%2,%3}, [%4];"
                 : "=r"(r[0]), "=r"(r[1]), "=r"(r[2]), "=r"(r[3]) : "r"(a));
}
static __device__ __forceinline__ void mma16816(float* d, const uint32_t* a,
                                                uint32_t b0, uint32_t b1) {
    asm volatile(
        "mma.sync.aligned.m16n8k16.row.col.f32.bf16.bf16.f32 "
        "{%0,%1,%2,%3}, {%4,%5,%6,%7}, {%8,%9}, {%0,%1,%2,%3};"
        : "+f"(d[0]), "+f"(d[1]), "+f"(d[2]), "+f"(d[3])
        : "r"(a[0]), "r"(a[1]), "r"(a[2]), "r"(a[3]), "r"(b0), "r"(b1));
}

template <int NTHR>
static __device__ __forceinline__ void load_tile(uint32_t sm, const bf16* g, int ld,
                                                 int rows, int tid) {
    for (int u = tid; u < rows * 8; u += NTHR) {
        int r = u >> 3, c = u & 7;
        cp16(sm + (uint32_t)(r * 128 + ((c ^ (r & 7)) << 4)), g + (size_t)r * ld + c * 8);
    }
}

// ---------------- launch 1: weight cvt + x transpose (fused) ----------------
__global__ void __launch_bounds__(256)
prep_kernel(const float* __restrict__ x, const float* __restrict__ Wk,
            const float* __restrict__ Wv, bf16* __restrict__ xt,
            bf16* __restrict__ Wkb, bf16* __restrict__ Wvb,
            unsigned* __restrict__ mbits) {
    if (blockIdx.y == 64) {   // cvt part: needs 1152 x-blocks
        const int i = blockIdx.x * 256 + threadIdx.x;
        if (blockIdx.x == 0 && threadIdx.x < PB) mbits[threadIdx.x] = 0u;
        if (i < PCK * PC) Wkb[i] = __float2bfloat16(Wk[i]);
        else if (i < PCK * PC + PC * PC) {
            int j = i - PCK * PC;
            Wvb[j] = __float2bfloat16(Wv[j]);
        }
        return;
    }
    // xT part: valid only for blockIdx.x < PN/32
    if (blockIdx.x >= PN / 32) return;
    __shared__ float tile[32][65];
    const int b = blockIdx.y >> 3;
    const int cslice = blockIdx.y & 7;
    const int n0 = blockIdx.x * 32, c0 = cslice * 64;
    const int tx = threadIdx.x & 31, ty = threadIdx.x >> 5;
    const float* xb = x + (size_t)b * PC * PN;
#pragma unroll
    for (int k = 0; k < 8; k++) {
        int cl = ty + k * 8;
        tile[tx][cl] = xb[(size_t)(c0 + cl) * PN + n0 + tx];
    }
    __syncthreads();
    const int nl = threadIdx.x >> 3;
    const int ub = (threadIdx.x & 7) * 8;
    const float* tr = &tile[nl][ub];
    __nv_bfloat162 p0 = __floats2bfloat162_rn(tr[0], tr[1]);
    __nv_bfloat162 p1 = __floats2bfloat162_rn(tr[2], tr[3]);
    __nv_bfloat162 p2 = __floats2bfloat162_rn(tr[4], tr[5]);
    __nv_bfloat162 p3 = __floats2bfloat162_rn(tr[6], tr[7]);
    uint4 v = make_uint4(*(uint32_t*)&p0, *(uint32_t*)&p1, *(uint32_t*)&p2, *(uint32_t*)&p3);
    *(uint4*)(xt + ((size_t)b * PN + n0 + nl) * PC + c0 + ub) = v;
}

// ---------------- launch 2: qk GEMM with fused row-norm/shift ----------------
#define QK_STG ((128 + 64) * 128)
#define QK_TOT (3 * QK_STG)

__global__ void __launch_bounds__(256)
qk_gemm(const bf16* __restrict__ xT, const bf16* __restrict__ Wkb,
        bf16* __restrict__ qkt, const float* __restrict__ bk,
        float* __restrict__ qn, unsigned* __restrict__ mbits) {
    extern __shared__ __align__(1024) char smem[];
    const uint32_t sbase = s2u(smem);
    const int tid = threadIdx.x;
    const int wid = tid >> 5;
    const int lane = tid & 31;
    const int wm = wid >> 2;
    const int wn = wid & 3;
    const int bz = blockIdx.z;
    const int m0 = blockIdx.y * 128;
    const int l15 = lane & 15;
    const int swz = lane & 7;
    const int cbase = lane >> 4;
    const int g = lane >> 2, tg = lane & 3;

    const bf16* Ab = xT + ((size_t)bz * PN + m0) * PC;
    const int nK = PC >> 6;

    float acc[4][2][4];
#pragma unroll
    for (int i = 0; i < 4; i++)
#pragma unroll
        for (int j = 0; j < 2; j++)
#pragma unroll
            for (int q = 0; q < 4; q++) acc[i][j][q] = 0.f;

#pragma unroll
    for (int j = 0; j < 2; j++) {
        uint32_t s = sbase + j * QK_STG;
        load_tile<256>(s, Ab + j * 64, PC, 128, tid);
        load_tile<256>(s + 16384, Wkb + j * 64, PC, 64, tid);
        asm volatile("cp.async.commit_group;");
    }

    for (int i = 0; i < nK; i++) {
        asm volatile("cp.async.wait_group 1;");
        __syncthreads();
        const int j = i + 2;
        if (j < nK) {
            uint32_t s = sbase + (j % 3) * QK_STG;
            load_tile<256>(s, Ab + j * 64, PC, 128, tid);
            load_tile<256>(s + 16384, Wkb + j * 64, PC, 64, tid);
        }
        asm volatile("cp.async.commit_group;");

        const uint32_t sA_ = sbase + (i % 3) * QK_STG;
        const uint32_t sB_ = sA_ + 16384;
#pragma unroll
        for (int ks = 0; ks < 4; ks++) {
            const int chunk = ks * 2 + cbase;
            uint32_t a[4][4];
#pragma unroll
            for (int mf = 0; mf < 4; mf++) {
                int row = wm * 64 + mf * 16 + l15;
                ldm4(sA_ + (uint32_t)(row * 128 + ((chunk ^ swz) << 4)), a[mf]);
            }
            uint32_t b[2][2];
            {
                uint32_t r[4];
                int row = wn * 16 + l15;
                ldm4(sB_ + (uint32_t)(row * 128 + ((chunk ^ swz) << 4)), r);
                b[0][0] = r[0]; b[0][1] = r[2];
                b[1][0] = r[1]; b[1][1] = r[3];
            }
#pragma unroll
            for (int mf = 0; mf < 4; mf++)
#pragma unroll
                for (int nf = 0; nf < 2; nf++)
                    mma16816(acc[mf][nf], a[mf], b[nf][0], b[nf][1]);
        }
    }
    __syncthreads();

    float (*rsum)[128] = (float(*)[128])smem;

#pragma unroll
    for (int mf = 0; mf < 4; mf++) {
        const int r0l = wm * 64 + mf * 16 + g;
        const int r1l = r0l + 8;
        float ss0 = 0.f, ss1 = 0.f;
#pragma unroll
        for (int nf = 0; nf < 2; nf++) {
            float* d = acc[mf][nf];
            const int col = wn * 16 + nf * 8 + tg * 2;
            const float b0 = __ldg(bk + col), b1 = __ldg(bk + col + 1);
            float v0 = d[0] + b0, v1 = d[1] + b1;
            float v2 = d[2] + b0, v3 = d[3] + b1;
            const size_t o0 = ((size_t)bz * PN + m0 + r0l) * PCK + col;
            const size_t o1 = ((size_t)bz * PN + m0 + r1l) * PCK + col;
            *(__nv_bfloat162*)(qkt + o0) = __floats2bfloat162_rn(v0, v1);
            *(__nv_bfloat162*)(qkt + o1) = __floats2bfloat162_rn(v2, v3);
            ss0 += v0 * v0 + v1 * v1;
            ss1 += v2 * v2 + v3 * v3;
        }
        ss0 += __shfl_xor_sync(0xFFFFFFFFu, ss0, 1);
        ss0 += __shfl_xor_sync(0xFFFFFFFFu, ss0, 2);
        ss1 += __shfl_xor_sync(0xFFFFFFFFu, ss1, 1);
        ss1 += __shfl_xor_sync(0xFFFFFFFFu, ss1, 2);
        if (tg == 0) {
            rsum[wn][r0l] = ss0;
            rsum[wn][r1l] = ss1;
        }
    }
    __syncthreads();
    if (tid < 128) {
        float tot = rsum[0][tid] + rsum[1][tid] + rsum[2][tid] + rsum[3][tid];
        float nv = sqrtf(tot);
        qn[bz * PN + m0 + tid] = nv;
        atomicMax(mbits + bz, __float_as_uint(nv));
    }
}

// ---------------- launch 3: scores + value (fused by blockIdx.y) ----------
#define SC_SA 0
#define SC_SB 16384
#define SC_SH 32768
#define SC_SL 33280
#define SV_TOT (3 * 32768)

__global__ void __launch_bounds__(256)
scores_value_kernel(const bf16* __restrict__ qkt, const float* __restrict__ qn,
                    const unsigned* __restrict__ mbits, bf16* __restrict__ E,
                    float* __restrict__ lp,
                    const bf16* __restrict__ Wvb, const bf16* __restrict__ xT,
                    bf16* __restrict__ vout, const float* __restrict__ bv) {
    extern __shared__ __align__(1024) char smem[];
    const uint32_t sb = s2u(smem);
    const int tid = threadIdx.x;
    const int wid = tid >> 5;
    const int lane = tid & 31;
    const int l15 = lane & 15;
    const int swz = lane & 7;
    const int cbase = lane >> 4;
    const int g = lane >> 2, tg = lane & 3;
    const int bz = blockIdx.z;

    if (blockIdx.y < 32) {
        // ======== scores branch ========
        const int wm = wid >> 2;
        const int wn = wid & 3;
        const int n0 = blockIdx.y * 128;
        const int mb = blockIdx.x;
        const int m0 = mb * 128;

        const bf16* base = qkt + (size_t)bz * PN * PCK;
        load_tile<256>(sb + SC_SA, base + (size_t)n0 * PCK, PCK, 128, tid);
        load_tile<256>(sb + SC_SB, base + (size_t)m0 * PCK, PCK, 128, tid);
        asm volatile("cp.async.commit_group;");
        if (tid < 128)
            *(float*)(smem + SC_SH + tid * 4) =
                qn[bz * PN + n0 + tid] * __uint_as_float(__ldg(mbits + bz));
        asm volatile("cp.async.wait_group 0;");
        __syncthreads();

        float acc[4][4][4];
#pragma unroll
        for (int i = 0; i < 4; i++)
#pragma unroll
            for (int j = 0; j < 4; j++)
#pragma unroll
                for (int q = 0; q < 4; q++) acc[i][j][q] = 0.f;

#pragma unroll
        for (int ks = 0; ks < 4; ks++) {
            const int chunk = ks * 2 + cbase;
            uint32_t a[4][4];
#pragma unroll
            for (int mf = 0; mf < 4; mf++) {
                int row = wm * 64 + mf * 16 + l15;
                ldm4(sb + SC_SA + (uint32_t)(row * 128 + ((chunk ^ swz) << 4)), a[mf]);
            }
            uint32_t b[4][2];
#pragma unroll
            for (int np = 0; np < 2; np++) {
                uint32_t r[4];
                int row = wn * 32 + np * 16 + l15;
                ldm4(sb + SC_SB + (uint32_t)(row * 128 + ((chunk ^ swz) << 4)), r);
                b[2 * np][0] = r[0]; b[2 * np][1] = r[2];
                b[2 * np + 1][0] = r[1]; b[2 * np + 1][1] = r[3];
            }
#pragma unroll
            for (int mf = 0; mf < 4; mf++)
#pragma unroll
                for (int nf = 0; nf < 4; nf++)
                    mma16816(acc[mf][nf], a[mf], b[nf][0], b[nf][1]);
        }

#pragma unroll
        for (int mf = 0; mf < 4; mf++) {
            const int r0 = wm * 64 + mf * 16 + g;
            const int r1 = r0 + 8;
            const float sh0 = *(float*)(smem + SC_SH + r0 * 4);
            const float sh1 = *(float*)(smem + SC_SH + r1 * 4);
            float s0 = 0.f, s1 = 0.f;
#pragma unroll
            for (int nf = 0; nf < 4; nf++) {
                float* d = acc[mf][nf];
                float e0 = __expf(d[0] - sh0), e1 = __expf(d[1] - sh0);
                float e2 = __expf(d[2] - sh1), e3 = __expf(d[3] - sh1);
                s0 += e0 + e1;
                s1 += e2 + e3;
                __nv_bfloat162 p01 = __floats2bfloat162_rn(e0, e1);
                __nv_bfloat162 p23 = __floats2bfloat162_rn(e2, e3);
                d[0] = __uint_as_float(*(uint32_t*)&p01);
                d[1] = __uint_as_float(*(uint32_t*)&p23);
            }
            s0 += __shfl_xor_sync(0xFFFFFFFFu, s0, 1);
            s0 += __shfl_xor_sync(0xFFFFFFFFu, s0, 2);
            s1 += __shfl_xor_sync(0xFFFFFFFFu, s1, 1);
            s1 += __shfl_xor_sync(0xFFFFFFFFu, s1, 2);
            if (tg == 0) {
                *(float*)(smem + SC_SL + (wn * 128 + r0) * 4) = s0;
                *(float*)(smem + SC_SL + (wn * 128 + r1) * 4) = s1;
            }
        }
        __syncthreads();

#pragma unroll
        for (int mf = 0; mf < 4; mf++) {
            const int rl0 = wm * 64 + mf * 16 + g;
#pragma unroll
            for (int nf = 0; nf < 4; nf++) {
                const float* d = acc[mf][nf];
                const uint32_t su = (uint32_t)((wn * 4 + nf) ^ g);
                *(uint32_t*)(smem + rl0 * 256 + su * 16 + tg * 4) = __float_as_uint(d[0]);
                *(uint32_t*)(smem + (rl0 + 8) * 256 + su * 16 + tg * 4) = __float_as_uint(d[1]);
            }
        }
        __syncthreads();

        {
            const int u = tid & 7;
#pragma unroll
            for (int it = 0; it < 4; it++) {
                const int rr = it * 32 + (tid >> 3);
                bf16* gb = E + ((size_t)bz * PN + n0 + rr) * PN + m0;
#pragma unroll
                for (int h = 0; h < 2; h++) {
                    const int uu = u + h * 8;
                    uint4 v = *(uint4*)(smem + rr * 256 + ((uu ^ (rr & 7)) << 4));
                    *(uint4*)(gb + uu * 8) = v;
                }
            }
        }

        if (tid < 128) {
            float l = *(float*)(smem + SC_SL + tid * 4)
                    + *(float*)(smem + SC_SL + (128 + tid) * 4)
                    + *(float*)(smem + SC_SL + (256 + tid) * 4)
                    + *(float*)(smem + SC_SL + (384 + tid) * 4);
            lp[((size_t)(bz * 32 + mb)) * PN + n0 + tid] = l;
        }
        return;
    }

    // ======== value branch ========
    {
        const int wm = wid >> 2;
        const int wn = wid & 3;
        const int m0 = (blockIdx.y - 32) * 128;
        const int n0 = blockIdx.x * 128;
        constexpr int VSTG = 32768;

        const bf16* Ab = Wvb + (size_t)m0 * PC;
        const bf16* Bb = xT + ((size_t)bz * PN + n0) * PC;
        const int nK = PC >> 6;

        float acc[4][4][4];
#pragma unroll
        for (int i = 0; i < 4; i++)
#pragma unroll
            for (int j = 0; j < 4; j++)
#pragma unroll
                for (int q = 0; q < 4; q++) acc[i][j][q] = 0.f;

#pragma unroll
        for (int j = 0; j < 2; j++) {
            uint32_t s = sb + j * VSTG;
            load_tile<256>(s, Ab + j * 64, PC, 128, tid);
            load_tile<256>(s + 16384, Bb + j * 64, PC, 128, tid);
            asm volatile("cp.async.commit_group;");
        }

        for (int i = 0; i < nK; i++) {
            asm volatile("cp.async.wait_group 1;");
            __syncthreads();
            const int j = i + 2;
            if (j < nK) {
                uint32_t s = sb + (j % 3) * VSTG;
                load_tile<256>(s, Ab + j * 64, PC, 128, tid);
                load_tile<256>(s + 16384, Bb + j * 64, PC, 128, tid);
            }
            asm volatile("cp.async.commit_group;");

            const uint32_t sA_ = sb + (i % 3) * VSTG;
            const uint32_t sB_ = sA_ + 16384;
#pragma unroll
            for (int ks = 0; ks < 4; ks++) {
                const int chunk = ks * 2 + cbase;
                uint32_t a[4][4];
#pragma unroll
                for (int mf = 0; mf < 4; mf++) {
                    int row = wm * 64 + mf * 16 + l15;
                    ldm4(sA_ + (uint32_t)(row * 128 + ((chunk ^ swz) << 4)), a[mf]);
                }
                uint32_t b[4][2];
#pragma unroll
                for (int np = 0; np < 2; np++) {
                    uint32_t r[4];
                    int row = wn * 32 + np * 16 + l15;
                    ldm4(sB_ + (uint32_t)(row * 128 + ((chunk ^ swz) << 4)), r);
                    b[2 * np][0] = r[0]; b[2 * np][1] = r[2];
                    b[2 * np + 1][0] = r[1]; b[2 * np + 1][1] = r[3];
                }
#pragma unroll
                for (int mf = 0; mf < 4; mf++)
#pragma unroll
                    for (int nf = 0; nf < 4; nf++)
                        mma16816(acc[mf][nf], a[mf], b[nf][0], b[nf][1]);
            }
        }
        asm volatile("cp.async.wait_group 0;");

#pragma unroll
        for (int mf = 0; mf < 4; mf++) {
#pragma unroll
            for (int nf = 0; nf < 4; nf++) {
                const float* d = acc[mf][nf];
                const int col = n0 + wn * 32 + nf * 8 + tg * 2;
                const size_t row0 = (size_t)m0 + wm * 64 + mf * 16 + g;
                const size_t row1 = row0 + 8;
                const float br0 = __ldg(bv + row0), br1 = __ldg(bv + row1);
                const size_t o0 = ((size_t)bz * PC + row0) * PN + col;
                const size_t o1 = ((size_t)bz * PC + row1) * PN + col;
                *(__nv_bfloat162*)(vout + o0) = __floats2bfloat162_rn(d[0] + br0, d[1] + br0);
                *(__nv_bfloat162*)(vout + o1) = __floats2bfloat162_rn(d[2] + br1, d[3] + br1);
            }
        }
    }
}

// ---------------- launch 4: PV GEMM (+fused lred) --------------------------
#define PV_AB 16384
#define PV_STG 32768
#define PV_GSM (3 * PV_STG)
#define PV_TOT (PV_GSM + 512)

__global__ void __launch_bounds__(128, 2)
pv_gemm(const bf16* __restrict__ vmat, const bf16* __restrict__ E,
        const float* __restrict__ lp, const float* __restrict__ gamma,
        const float* __restrict__ x, float* __restrict__ out) {
    extern __shared__ __align__(1024) char smem[];
    const uint32_t sb = s2u(smem);
    const int tid = threadIdx.x;
    const int wid = tid >> 5;
    const int lane = tid & 31;
    const int wm = wid & 1;
    const int wn = wid >> 1;
    const int l15 = lane & 15;
    const int swz = lane & 7;
    const int cbase = lane >> 4;
    const int g = lane >> 2, tg = lane & 3;
    const int bz = blockIdx.z;
    const int c0 = blockIdx.y * 128;
    const int n0 = blockIdx.x * 128;

    float* gsm = (float*)(smem + PV_GSM);
    if (tid < 128) {
        float l = 0.f;
#pragma unroll
        for (int xb = 0; xb < 32; xb++)
            l += lp[((size_t)(bz * 32 + xb)) * PN + n0 + tid];
        gsm[tid] = __ldg(gamma) / l;
    }

    const bf16* Ab = vmat + ((size_t)bz * PC + c0) * PN;
    const bf16* Bb = E + ((size_t)bz * PN + n0) * PN;
    const int nK = PN >> 6;

    float acc[4][8][4];
#pragma unroll
    for (int i = 0; i < 4; i++)
#pragma unroll
        for (int j = 0; j < 8; j++)
#pragma unroll
            for (int q = 0; q < 4; q++) acc[i][j][q] = 0.f;

#pragma unroll
    for (int j = 0; j < 2; j++) {
        uint32_t s = sb + j * PV_STG;
        load_tile<128>(s, Ab + j * 64, PN, 128, tid);
        load_tile<128>(s + PV_AB, Bb + j * 64, PN, 128, tid);
        asm volatile("cp.async.commit_group;");
    }

#pragma unroll 1
    for (int i = 0; i < nK; i++) {
        asm volatile("cp.async.wait_group 1;");
        __syncthreads();
        const int j = i + 2;
        if (j < nK) {
            uint32_t s = sb + (j % 3) * PV_STG;
            load_tile<128>(s, Ab + j * 64, PN, 128, tid);
            load_tile<128>(s + PV_AB, Bb + j * 64, PN, 128, tid);
        }
        asm volatile("cp.async.commit_group;");

        const uint32_t sA_ = sb + (i % 3) * PV_STG;
        const uint32_t sB_ = sA_ + PV_AB;
#pragma unroll
        for (int ks = 0; ks < 4; ks++) {
            const int chunk = ks * 2 + cbase;
            uint32_t a[4][4];
#pragma unroll
            for (int mf = 0; mf < 4; mf++) {
                int row = wm * 64 + mf * 16 + l15;
                ldm4(sA_ + (uint32_t)(row * 128 + ((chunk ^ swz) << 4)), a[mf]);
            }
            uint32_t b[8][2];
#pragma unroll
            for (int np = 0; np < 4; np++) {
                uint32_t r[4];
                int row = wn * 64 + np * 16 + l15;
                ldm4(sB_ + (uint32_t)(row * 128 + ((chunk ^ swz) << 4)), r);
                b[2 * np][0] = r[0]; b[2 * np][1] = r[2];
                b[2 * np + 1][0] = r[1]; b[2 * np + 1][1] = r[3];
            }
#pragma unroll
            for (int mf = 0; mf < 4; mf++)
#pragma unroll
                for (int nf = 0; nf < 8; nf++)
                    mma16816(acc[mf][nf], a[mf], b[nf][0], b[nf][1]);
        }
    }
    asm volatile("cp.async.wait_group 0;");

#pragma unroll
    for (int mf = 0; mf < 4; mf++) {
#pragma unroll
        for (int nf = 0; nf < 8; nf++) {
            const float* d = acc[mf][nf];
            const int lcol = wn * 64 + nf * 8 + tg * 2;
            const int col = n0 + lcol;
            const float gi0 = gsm[lcol];
            const float gi1 = gsm[lcol + 1];
            const size_t row0 = (size_t)c0 + wm * 64 + mf * 16 + g;
            const size_t row1 = row0 + 8;
            const size_t o0 = ((size_t)bz * PC + row0) * PN + col;
            const size_t o1 = ((size_t)bz * PC + row1) * PN + col;
            float2 x0 = *(const float2*)(x + o0);
            float2 x1 = *(const float2*)(x + o1);
            *(float2*)(out + o0) = make_float2(fmaf(gi0, d[0], x0.x), fmaf(gi1, d[1], x0.y));
            *(float2*)(out + o1) = make_float2(fmaf(gi0, d[2], x1.x), fmaf(gi1, d[3], x1.y));
        }
    }
}

// ---------------- launch ----------------
extern "C" void kernel_launch(void* const* d_in, const int* in_sizes, int n_in,
                              void* d_out, int out_size) {
    const float* x     = (const float*)d_in[0];
    const float* Wk    = (const float*)d_in[1];
    const float* bk    = (const float*)d_in[2];
    const float* Wv    = (const float*)d_in[3];
    const float* bv    = (const float*)d_in[4];
    const float* gamma = (const float*)d_in[5];
    float* out = (float*)d_out;

    bf16 *p_xT, *p_Wkb, *p_Wvb, *p_qkt, *p_v, *p_E;
    float *p_qn, *p_lp;
    unsigned* p_mbits;
    cudaGetSymbolAddress((void**)&p_xT,    g_xT);
    cudaGetSymbolAddress((void**)&p_Wkb,   g_Wkb);
    cudaGetSymbolAddress((void**)&p_Wvb,   g_Wvb);
    cudaGetSymbolAddress((void**)&p_qkt,   g_qkt);
    cudaGetSymbolAddress((void**)&p_v,     g_v);
    cudaGetSymbolAddress((void**)&p_E,     g_E);
    cudaGetSymbolAddress((void**)&p_qn,    g_qn);
    cudaGetSymbolAddress((void**)&p_mbits, g_mbits);
    cudaGetSymbolAddress((void**)&p_lp,    g_lp);

    cudaFuncSetAttribute(qk_gemm, cudaFuncAttributeMaxDynamicSharedMemorySize, QK_TOT);
    cudaFuncSetAttribute(scores_value_kernel, cudaFuncAttributeMaxDynamicSharedMemorySize, SV_TOT);
    cudaFuncSetAttribute(pv_gemm, cudaFuncAttributeMaxDynamicSharedMemorySize, PV_TOT);

    // 1) prep: weight converts (y==64, x<1152) + x transpose (y<64, x<128)
    prep_kernel<<<dim3(1152, 65, 1), 256>>>(x, Wk, Wv, p_xT, p_Wkb, p_Wvb, p_mbits);

    // 2) qkt + fused row norms / max
    qk_gemm<<<dim3(1, PN / 128, PB), 256, QK_TOT>>>(p_xT, p_Wkb, p_qkt, bk, p_qn, p_mbits);

    // 3) scores (y<32) + value (y in [32,36))
    scores_value_kernel<<<dim3(PN / 128, 36, PB), 256, SV_TOT>>>(
        p_qkt, p_qn, p_mbits, p_E, p_lp, p_Wvb, p_xT, p_v, bv);

    // 4) PV (+fused lred)   (<- profiled launch)
    pv_gemm<<<dim3(PN / 128, PC / 128, PB), 128, PV_TOT>>>(p_v, p_E, p_lp, gamma, x, out);
}

// round 16
// speedup vs baseline: 1.0718x; 1.0718x over previous
#include <cuda_runtime.h>
#include <cuda_bf16.h>
#include <cstdint>
#include <cstddef>

#define PB 4
#define PC 512
#define PCK 64
#define PN 4096

typedef __nv_bfloat16 bf16;

// ---------------- static scratch ----------------
__device__ bf16     g_xT[(size_t)PB * PN * PC];     // [b][n][c]
__device__ bf16     g_Wkb[PCK * PC];
__device__ bf16     g_Wvb[PC * PC];
__device__ bf16     g_qkt[(size_t)PB * PN * PCK];   // [b][n][ck]
__device__ bf16     g_v[(size_t)PB * PC * PN];      // [b][c][m]
__device__ bf16     g_E[(size_t)PB * PN * PN];      // [b][n][m]
__device__ float    g_qn[PB * PN];
__device__ unsigned g_mbits[PB];
__device__ float    g_lp[(size_t)PB * 32 * PN];

// ---------------- helpers ----------------
static __device__ __forceinline__ uint32_t s2u(const void* p) {
    uint32_t a;
    asm("{ .reg .u64 t; cvta.to.shared.u64 t, %1; cvt.u32.u64 %0, t; }" : "=r"(a) : "l"(p));
    return a;
}
static __device__ __forceinline__ void cp16(uint32_t dst, const void* src) {
    asm volatile("cp.async.cg.shared.global [%0], [%1], 16;" :: "r"(dst), "l"(src));
}
static __device__ __forceinline__ void ldm4(uint32_t a, uint32_t* r) {
    asm volatile("ldmatrix.sync.aligned.m8n8.x4.shared.b16 {%0,%1,%2,%3}, [%4];"
                 : "=r"(r[0]), "=r"(r[1]), "=r"(r[2]), "=r"(r[3]) : "r"(a));
}
static __device__ __forceinline__ void mma16816(float* d, const uint32_t* a,
                                                uint32_t b0, uint32_t b1) {
    asm volatile(
        "mma.sync.aligned.m16n8k16.row.col.f32.bf16.bf16.f32 "
        "{%0,%1,%2,%3}, {%4,%5,%6,%7}, {%8,%9}, {%0,%1,%2,%3};"
        : "+f"(d[0]), "+f"(d[1]), "+f"(d[2]), "+f"(d[3])
        : "r"(a[0]), "r"(a[1]), "r"(a[2]), "r"(a[3]), "r"(b0), "r"(b1));
}

template <int NTHR>
static __device__ __forceinline__ void load_tile(uint32_t sm, const bf16* g, int ld,
                                                 int rows, int tid) {
    for (int u = tid; u < rows * 8; u += NTHR) {
        int r = u >> 3, c = u & 7;
        cp16(sm + (uint32_t)(r * 128 + ((c ^ (r & 7)) << 4)), g + (size_t)r * ld + c * 8);
    }
}

// ---------------- qk GEMM with fused row-norm/shift epilogue ----------------
#define QK_STG ((128 + 64) * 128)
#define QK_TOT (3 * QK_STG)

__global__ void __launch_bounds__(256)
qk_gemm(const bf16* __restrict__ xT, const bf16* __restrict__ Wkb,
        bf16* __restrict__ qkt, const float* __restrict__ bk,
        float* __restrict__ qn, unsigned* __restrict__ mbits) {
    extern __shared__ __align__(1024) char smem[];
    const uint32_t sbase = s2u(smem);
    const int tid = threadIdx.x;
    const int wid = tid >> 5;
    const int lane = tid & 31;
    const int wm = wid >> 2;
    const int wn = wid & 3;
    const int bz = blockIdx.z;
    const int m0 = blockIdx.y * 128;
    const int l15 = lane & 15;
    const int swz = lane & 7;
    const int cbase = lane >> 4;
    const int g = lane >> 2, tg = lane & 3;

    const bf16* Ab = xT + ((size_t)bz * PN + m0) * PC;
    const int nK = PC >> 6;

    float acc[4][2][4];
#pragma unroll
    for (int i = 0; i < 4; i++)
#pragma unroll
        for (int j = 0; j < 2; j++)
#pragma unroll
            for (int q = 0; q < 4; q++) acc[i][j][q] = 0.f;

#pragma unroll
    for (int j = 0; j < 2; j++) {
        uint32_t s = sbase + j * QK_STG;
        load_tile<256>(s, Ab + j * 64, PC, 128, tid);
        load_tile<256>(s + 16384, Wkb + j * 64, PC, 64, tid);
        asm volatile("cp.async.commit_group;");
    }

    for (int i = 0; i < nK; i++) {
        asm volatile("cp.async.wait_group 1;");
        __syncthreads();
        const int j = i + 2;
        if (j < nK) {
            uint32_t s = sbase + (j % 3) * QK_STG;
            load_tile<256>(s, Ab + j * 64, PC, 128, tid);
            load_tile<256>(s + 16384, Wkb + j * 64, PC, 64, tid);
        }
        asm volatile("cp.async.commit_group;");

        const uint32_t sA_ = sbase + (i % 3) * QK_STG;
        const uint32_t sB_ = sA_ + 16384;
#pragma unroll
        for (int ks = 0; ks < 4; ks++) {
            const int chunk = ks * 2 + cbase;
            uint32_t a[4][4];
#pragma unroll
            for (int mf = 0; mf < 4; mf++) {
                int row = wm * 64 + mf * 16 + l15;
                ldm4(sA_ + (uint32_t)(row * 128 + ((chunk ^ swz) << 4)), a[mf]);
            }
            uint32_t b[2][2];
            {
                uint32_t r[4];
                int row = wn * 16 + l15;
                ldm4(sB_ + (uint32_t)(row * 128 + ((chunk ^ swz) << 4)), r);
                b[0][0] = r[0]; b[0][1] = r[2];
                b[1][0] = r[1]; b[1][1] = r[3];
            }
#pragma unroll
            for (int mf = 0; mf < 4; mf++)
#pragma unroll
                for (int nf = 0; nf < 2; nf++)
                    mma16816(acc[mf][nf], a[mf], b[nf][0], b[nf][1]);
        }
    }
    __syncthreads();

    float (*rsum)[128] = (float(*)[128])smem;

#pragma unroll
    for (int mf = 0; mf < 4; mf++) {
        const int r0l = wm * 64 + mf * 16 + g;
        const int r1l = r0l + 8;
        float ss0 = 0.f, ss1 = 0.f;
#pragma unroll
        for (int nf = 0; nf < 2; nf++) {
            float* d = acc[mf][nf];
            const int col = wn * 16 + nf * 8 + tg * 2;
            const float b0 = __ldg(bk + col), b1 = __ldg(bk + col + 1);
            float v0 = d[0] + b0, v1 = d[1] + b1;
            float v2 = d[2] + b0, v3 = d[3] + b1;
            const size_t o0 = ((size_t)bz * PN + m0 + r0l) * PCK + col;
            const size_t o1 = ((size_t)bz * PN + m0 + r1l) * PCK + col;
            *(__nv_bfloat162*)(qkt + o0) = __floats2bfloat162_rn(v0, v1);
            *(__nv_bfloat162*)(qkt + o1) = __floats2bfloat162_rn(v2, v3);
            ss0 += v0 * v0 + v1 * v1;
            ss1 += v2 * v2 + v3 * v3;
        }
        ss0 += __shfl_xor_sync(0xFFFFFFFFu, ss0, 1);
        ss0 += __shfl_xor_sync(0xFFFFFFFFu, ss0, 2);
        ss1 += __shfl_xor_sync(0xFFFFFFFFu, ss1, 1);
        ss1 += __shfl_xor_sync(0xFFFFFFFFu, ss1, 2);
        if (tg == 0) {
            rsum[wn][r0l] = ss0;
            rsum[wn][r1l] = ss1;
        }
    }
    __syncthreads();
    if (tid < 128) {
        float tot = rsum[0][tid] + rsum[1][tid] + rsum[2][tid] + rsum[3][tid];
        float nv = sqrtf(tot);
        qn[bz * PN + m0 + tid] = nv;
        atomicMax(mbits + bz, __float_as_uint(nv));
    }
}

// ---------------- scores kernel: staged coalesced E stores ----------------
#define SC_SA 0
#define SC_SB 16384
#define SC_SH 32768
#define SC_SL 33280
#define SC_TOT 35328

__global__ void __launch_bounds__(256)
scores_kernel(const bf16* __restrict__ qkt, const float* __restrict__ qn,
              const unsigned* __restrict__ mbits, bf16* __restrict__ E,
              float* __restrict__ lp) {
    extern __shared__ __align__(1024) char smem[];
    const uint32_t sb = s2u(smem);
    const int tid = threadIdx.x;
    const int wid = tid >> 5;
    const int lane = tid & 31;
    const int wm = wid >> 2;
    const int wn = wid & 3;
    const int l15 = lane & 15;
    const int swz = lane & 7;
    const int cbase = lane >> 4;
    const int g = lane >> 2, tg = lane & 3;
    const int bz = blockIdx.z;
    const int n0 = blockIdx.y * 128;
    const int mb = blockIdx.x;
    const int m0 = mb * 128;

    const bf16* base = qkt + (size_t)bz * PN * PCK;
    load_tile<256>(sb + SC_SA, base + (size_t)n0 * PCK, PCK, 128, tid);
    load_tile<256>(sb + SC_SB, base + (size_t)m0 * PCK, PCK, 128, tid);
    asm volatile("cp.async.commit_group;");
    if (tid < 128)
        *(float*)(smem + SC_SH + tid * 4) =
            qn[bz * PN + n0 + tid] * __uint_as_float(__ldg(mbits + bz));
    asm volatile("cp.async.wait_group 0;");
    __syncthreads();

    float acc[4][4][4];
#pragma unroll
    for (int i = 0; i < 4; i++)
#pragma unroll
        for (int j = 0; j < 4; j++)
#pragma unroll
            for (int q = 0; q < 4; q++) acc[i][j][q] = 0.f;

#pragma unroll
    for (int ks = 0; ks < 4; ks++) {
        const int chunk = ks * 2 + cbase;
        uint32_t a[4][4];
#pragma unroll
        for (int mf = 0; mf < 4; mf++) {
            int row = wm * 64 + mf * 16 + l15;
            ldm4(sb + SC_SA + (uint32_t)(row * 128 + ((chunk ^ swz) << 4)), a[mf]);
        }
        uint32_t b[4][2];
#pragma unroll
        for (int np = 0; np < 2; np++) {
            uint32_t r[4];
            int row = wn * 32 + np * 16 + l15;
            ldm4(sb + SC_SB + (uint32_t)(row * 128 + ((chunk ^ swz) << 4)), r);
            b[2 * np][0] = r[0]; b[2 * np][1] = r[2];
            b[2 * np + 1][0] = r[1]; b[2 * np + 1][1] = r[3];
        }
#pragma unroll
        for (int mf = 0; mf < 4; mf++)
#pragma unroll
            for (int nf = 0; nf < 4; nf++)
                mma16816(acc[mf][nf], a[mf], b[nf][0], b[nf][1]);
    }

    // convert in place (exp+pack) and produce partial row sums
#pragma unroll
    for (int mf = 0; mf < 4; mf++) {
        const int r0 = wm * 64 + mf * 16 + g;
        const int r1 = r0 + 8;
        const float sh0 = *(float*)(smem + SC_SH + r0 * 4);
        const float sh1 = *(float*)(smem + SC_SH + r1 * 4);
        float s0 = 0.f, s1 = 0.f;
#pragma unroll
        for (int nf = 0; nf < 4; nf++) {
            float* d = acc[mf][nf];
            float e0 = __expf(d[0] - sh0), e1 = __expf(d[1] - sh0);
            float e2 = __expf(d[2] - sh1), e3 = __expf(d[3] - sh1);
            s0 += e0 + e1;
            s1 += e2 + e3;
            __nv_bfloat162 p01 = __floats2bfloat162_rn(e0, e1);
            __nv_bfloat162 p23 = __floats2bfloat162_rn(e2, e3);
            d[0] = __uint_as_float(*(uint32_t*)&p01);
            d[1] = __uint_as_float(*(uint32_t*)&p23);
        }
        s0 += __shfl_xor_sync(0xFFFFFFFFu, s0, 1);
        s0 += __shfl_xor_sync(0xFFFFFFFFu, s0, 2);
        s1 += __shfl_xor_sync(0xFFFFFFFFu, s1, 1);
        s1 += __shfl_xor_sync(0xFFFFFFFFu, s1, 2);
        if (tg == 0) {
            *(float*)(smem + SC_SL + (wn * 128 + r0) * 4) = s0;
            *(float*)(smem + SC_SL + (wn * 128 + r1) * 4) = s1;
        }
    }
    __syncthreads();

    // stage bf16 E tile
#pragma unroll
    for (int mf = 0; mf < 4; mf++) {
        const int rl0 = wm * 64 + mf * 16 + g;
#pragma unroll
        for (int nf = 0; nf < 4; nf++) {
            const float* d = acc[mf][nf];
            const uint32_t su = (uint32_t)((wn * 4 + nf) ^ g);
            *(uint32_t*)(smem + rl0 * 256 + su * 16 + tg * 4) = __float_as_uint(d[0]);
            *(uint32_t*)(smem + (rl0 + 8) * 256 + su * 16 + tg * 4) = __float_as_uint(d[1]);
        }
    }
    __syncthreads();

    // flush: 128 rows x 256B, 128B-contiguous per 8 lanes
    {
        const int u = tid & 7;
#pragma unroll
        for (int it = 0; it < 4; it++) {
            const int rr = it * 32 + (tid >> 3);
            bf16* gb = E + ((size_t)bz * PN + n0 + rr) * PN + m0;
#pragma unroll
            for (int h = 0; h < 2; h++) {
                const int uu = u + h * 8;
                uint4 v = *(uint4*)(smem + rr * 256 + ((uu ^ (rr & 7)) << 4));
                *(uint4*)(gb + uu * 8) = v;
            }
        }
    }

    if (tid < 128) {
        float l = *(float*)(smem + SC_SL + tid * 4)
                + *(float*)(smem + SC_SL + (128 + tid) * 4)
                + *(float*)(smem + SC_SL + (256 + tid) * 4)
                + *(float*)(smem + SC_SL + (384 + tid) * 4);
        lp[((size_t)(bz * 32 + mb)) * PN + n0 + tid] = l;
    }
}

// ---------------- value GEMM (128 thr, 2 CTAs/SM) ----------
#define VG_AB 16384
#define VG_STG 32768
#define VG_TOT (3 * VG_STG)

__global__ void __launch_bounds__(128, 2)
value_gemm(const bf16* __restrict__ Wvb, const bf16* __restrict__ xT,
           bf16* __restrict__ vout, const float* __restrict__ bv) {
    extern __shared__ __align__(1024) char smem[];
    const uint32_t sb = s2u(smem);
    const int tid = threadIdx.x;
    const int wid = tid >> 5;
    const int lane = tid & 31;
    const int wm = wid & 1;
    const int wn = wid >> 1;
    const int l15 = lane & 15;
    const int swz = lane & 7;
    const int cbase = lane >> 4;
    const int g = lane >> 2, tg = lane & 3;
    const int bz = blockIdx.z;
    const int m0 = blockIdx.y * 128;
    const int n0 = blockIdx.x * 128;

    const bf16* Ab = Wvb + (size_t)m0 * PC;
    const bf16* Bb = xT + ((size_t)bz * PN + n0) * PC;
    const int nK = PC >> 6;

    float acc[4][8][4];
#pragma unroll
    for (int i = 0; i < 4; i++)
#pragma unroll
        for (int j = 0; j < 8; j++)
#pragma unroll
            for (int q = 0; q < 4; q++) acc[i][j][q] = 0.f;

#pragma unroll
    for (int j = 0; j < 2; j++) {
        uint32_t s = sb + j * VG_STG;
        load_tile<128>(s, Ab + j * 64, PC, 128, tid);
        load_tile<128>(s + VG_AB, Bb + j * 64, PC, 128, tid);
        asm volatile("cp.async.commit_group;");
    }

#pragma unroll 1
    for (int i = 0; i < nK; i++) {
        asm volatile("cp.async.wait_group 1;");
        __syncthreads();
        const int j = i + 2;
        if (j < nK) {
            uint32_t s = sb + (j % 3) * VG_STG;
            load_tile<128>(s, Ab + j * 64, PC, 128, tid);
            load_tile<128>(s + VG_AB, Bb + j * 64, PC, 128, tid);
        }
        asm volatile("cp.async.commit_group;");

        const uint32_t sA_ = sb + (i % 3) * VG_STG;
        const uint32_t sB_ = sA_ + VG_AB;
#pragma unroll
        for (int ks = 0; ks < 4; ks++) {
            const int chunk = ks * 2 + cbase;
            uint32_t a[4][4];
#pragma unroll
            for (int mf = 0; mf < 4; mf++) {
                int row = wm * 64 + mf * 16 + l15;
                ldm4(sA_ + (uint32_t)(row * 128 + ((chunk ^ swz) << 4)), a[mf]);
            }
            uint32_t b[8][2];
#pragma unroll
            for (int np = 0; np < 4; np++) {
                uint32_t r[4];
                int row = wn * 64 + np * 16 + l15;
                ldm4(sB_ + (uint32_t)(row * 128 + ((chunk ^ swz) << 4)), r);
                b[2 * np][0] = r[0]; b[2 * np][1] = r[2];
                b[2 * np + 1][0] = r[1]; b[2 * np + 1][1] = r[3];
            }
#pragma unroll
            for (int mf = 0; mf < 4; mf++)
#pragma unroll
                for (int nf = 0; nf < 8; nf++)
                    mma16816(acc[mf][nf], a[mf], b[nf][0], b[nf][1]);
        }
    }
    asm volatile("cp.async.wait_group 0;");

#pragma unroll
    for (int mf = 0; mf < 4; mf++) {
#pragma unroll
        for (int nf = 0; nf < 8; nf++) {
            const float* d = acc[mf][nf];
            const int col = n0 + wn * 64 + nf * 8 + tg * 2;
            const size_t row0 = (size_t)m0 + wm * 64 + mf * 16 + g;
            const size_t row1 = row0 + 8;
            const float br0 = __ldg(bv + row0), br1 = __ldg(bv + row1);
            const size_t o0 = ((size_t)bz * PC + row0) * PN + col;
            const size_t o1 = ((size_t)bz * PC + row1) * PN + col;
            *(__nv_bfloat162*)(vout + o0) = __floats2bfloat162_rn(d[0] + br0, d[1] + br0);
            *(__nv_bfloat162*)(vout + o1) = __floats2bfloat162_rn(d[2] + br1, d[3] + br1);
        }
    }
}

// ---------------- PV GEMM (R10 body + fused lred) ----------------
#define PV_AB 16384
#define PV_STG 32768
#define PV_GSM (3 * PV_STG)
#define PV_TOT (PV_GSM + 512)

__global__ void __launch_bounds__(128, 2)
pv_gemm(const bf16* __restrict__ vmat, const bf16* __restrict__ E,
        const float* __restrict__ lp, const float* __restrict__ gamma,
        const float* __restrict__ x, float* __restrict__ out) {
    extern __shared__ __align__(1024) char smem[];
    const uint32_t sb = s2u(smem);
    const int tid = threadIdx.x;
    const int wid = tid >> 5;
    const int lane = tid & 31;
    const int wm = wid & 1;
    const int wn = wid >> 1;
    const int l15 = lane & 15;
    const int swz = lane & 7;
    const int cbase = lane >> 4;
    const int g = lane >> 2, tg = lane & 3;
    const int bz = blockIdx.z;
    const int c0 = blockIdx.y * 128;
    const int n0 = blockIdx.x * 128;

    // fused lred
    float* gsm = (float*)(smem + PV_GSM);
    if (tid < 128) {
        float l = 0.f;
#pragma unroll
        for (int xb = 0; xb < 32; xb++)
            l += lp[((size_t)(bz * 32 + xb)) * PN + n0 + tid];
        gsm[tid] = __ldg(gamma) / l;
    }

    const bf16* Ab = vmat + ((size_t)bz * PC + c0) * PN;
    const bf16* Bb = E + ((size_t)bz * PN + n0) * PN;
    const int nK = PN >> 6;

    float acc[4][8][4];
#pragma unroll
    for (int i = 0; i < 4; i++)
#pragma unroll
        for (int j = 0; j < 8; j++)
#pragma unroll
            for (int q = 0; q < 4; q++) acc[i][j][q] = 0.f;

#pragma unroll
    for (int j = 0; j < 2; j++) {
        uint32_t s = sb + j * PV_STG;
        load_tile<128>(s, Ab + j * 64, PN, 128, tid);
        load_tile<128>(s + PV_AB, Bb + j * 64, PN, 128, tid);
        asm volatile("cp.async.commit_group;");
    }

#pragma unroll 1
    for (int i = 0; i < nK; i++) {
        asm volatile("cp.async.wait_group 1;");
        __syncthreads();
        const int j = i + 2;
        if (j < nK) {
            uint32_t s = sb + (j % 3) * PV_STG;
            load_tile<128>(s, Ab + j * 64, PN, 128, tid);
            load_tile<128>(s + PV_AB, Bb + j * 64, PN, 128, tid);
        }
        asm volatile("cp.async.commit_group;");

        const uint32_t sA_ = sb + (i % 3) * PV_STG;
        const uint32_t sB_ = sA_ + PV_AB;
#pragma unroll
        for (int ks = 0; ks < 4; ks++) {
            const int chunk = ks * 2 + cbase;
            uint32_t a[4][4];
#pragma unroll
            for (int mf = 0; mf < 4; mf++) {
                int row = wm * 64 + mf * 16 + l15;
                ldm4(sA_ + (uint32_t)(row * 128 + ((chunk ^ swz) << 4)), a[mf]);
            }
            uint32_t b[8][2];
#pragma unroll
            for (int np = 0; np < 4; np++) {
                uint32_t r[4];
                int row = wn * 64 + np * 16 + l15;
                ldm4(sB_ + (uint32_t)(row * 128 + ((chunk ^ swz) << 4)), r);
                b[2 * np][0] = r[0]; b[2 * np][1] = r[2];
                b[2 * np + 1][0] = r[1]; b[2 * np + 1][1] = r[3];
            }
#pragma unroll
            for (int mf = 0; mf < 4; mf++)
#pragma unroll
                for (int nf = 0; nf < 8; nf++)
                    mma16816(acc[mf][nf], a[mf], b[nf][0], b[nf][1]);
        }
    }
    asm volatile("cp.async.wait_group 0;");

#pragma unroll
    for (int mf = 0; mf < 4; mf++) {
#pragma unroll
        for (int nf = 0; nf < 8; nf++) {
            const float* d = acc[mf][nf];
            const int lcol = wn * 64 + nf * 8 + tg * 2;
            const int col = n0 + lcol;
            const float gi0 = gsm[lcol];
            const float gi1 = gsm[lcol + 1];
            const size_t row0 = (size_t)c0 + wm * 64 + mf * 16 + g;
            const size_t row1 = row0 + 8;
            const size_t o0 = ((size_t)bz * PC + row0) * PN + col;
            const size_t o1 = ((size_t)bz * PC + row1) * PN + col;
            float2 x0 = *(const float2*)(x + o0);
            float2 x1 = *(const float2*)(x + o1);
            *(float2*)(out + o0) = make_float2(fmaf(gi0, d[0], x0.x), fmaf(gi1, d[1], x0.y));
            *(float2*)(out + o1) = make_float2(fmaf(gi0, d[2], x1.x), fmaf(gi1, d[3], x1.y));
        }
    }
}

// ---------------- prep kernels ----------------
__global__ void __launch_bounds__(256) xT_kernel(const float* __restrict__ x,
                                                 bf16* __restrict__ xt) {
    __shared__ float tile[32][65];
    const int b = blockIdx.z;
    const int n0 = blockIdx.x * 32, c0 = blockIdx.y * 64;
    const int tx = threadIdx.x & 31, ty = threadIdx.x >> 5;
    const float* xb = x + (size_t)b * PC * PN;
#pragma unroll
    for (int k = 0; k < 8; k++) {
        int cl = ty + k * 8;
        tile[tx][cl] = xb[(size_t)(c0 + cl) * PN + n0 + tx];
    }
    __syncthreads();
    const int nl = threadIdx.x >> 3;
    const int ub = (threadIdx.x & 7) * 8;
    const float* tr = &tile[nl][ub];
    __nv_bfloat162 p0 = __floats2bfloat162_rn(tr[0], tr[1]);
    __nv_bfloat162 p1 = __floats2bfloat162_rn(tr[2], tr[3]);
    __nv_bfloat162 p2 = __floats2bfloat162_rn(tr[4], tr[5]);
    __nv_bfloat162 p3 = __floats2bfloat162_rn(tr[6], tr[7]);
    uint4 v = make_uint4(*(uint32_t*)&p0, *(uint32_t*)&p1, *(uint32_t*)&p2, *(uint32_t*)&p3);
    *(uint4*)(xt + ((size_t)b * PN + n0 + nl) * PC + c0 + ub) = v;
}

__global__ void __launch_bounds__(256)
cvt_all(const float* __restrict__ Wk, const float* __restrict__ Wv,
        bf16* __restrict__ Wkb, bf16* __restrict__ Wvb,
        unsigned* __restrict__ mbits) {
    const int i = blockIdx.x * 256 + threadIdx.x;
    if (blockIdx.x == 0 && threadIdx.x < PB) mbits[threadIdx.x] = 0u;
    if (i < PCK * PC) Wkb[i] = __float2bfloat16(Wk[i]);
    else if (i < PCK * PC + PC * PC) {
        int j = i - PCK * PC;
        Wvb[j] = __float2bfloat16(Wv[j]);
    }
}

// ---------------- launch ----------------
extern "C" void kernel_launch(void* const* d_in, const int* in_sizes, int n_in,
                              void* d_out, int out_size) {
    const float* x     = (const float*)d_in[0];
    const float* Wk    = (const float*)d_in[1];
    const float* bk    = (const float*)d_in[2];
    const float* Wv    = (const float*)d_in[3];
    const float* bv    = (const float*)d_in[4];
    const float* gamma = (const float*)d_in[5];
    float* out = (float*)d_out;

    bf16 *p_xT, *p_Wkb, *p_Wvb, *p_qkt, *p_v, *p_E;
    float *p_qn, *p_lp;
    unsigned* p_mbits;
    cudaGetSymbolAddress((void**)&p_xT,    g_xT);
    cudaGetSymbolAddress((void**)&p_Wkb,   g_Wkb);
    cudaGetSymbolAddress((void**)&p_Wvb,   g_Wvb);
    cudaGetSymbolAddress((void**)&p_qkt,   g_qkt);
    cudaGetSymbolAddress((void**)&p_v,     g_v);
    cudaGetSymbolAddress((void**)&p_E,     g_E);
    cudaGetSymbolAddress((void**)&p_qn,    g_qn);
    cudaGetSymbolAddress((void**)&p_mbits, g_mbits);
    cudaGetSymbolAddress((void**)&p_lp,    g_lp);

    cudaFuncSetAttribute(qk_gemm,       cudaFuncAttributeMaxDynamicSharedMemorySize, QK_TOT);
    cudaFuncSetAttribute(value_gemm,    cudaFuncAttributeMaxDynamicSharedMemorySize, VG_TOT);
    cudaFuncSetAttribute(scores_kernel, cudaFuncAttributeMaxDynamicSharedMemorySize, SC_TOT);
    cudaFuncSetAttribute(pv_gemm,       cudaFuncAttributeMaxDynamicSharedMemorySize, PV_TOT);

    // 1) weight converts + mbits zero
    cvt_all<<<(PCK * PC + PC * PC + 255) / 256, 256>>>(Wk, Wv, p_Wkb, p_Wvb, p_mbits);

    // 2) x transpose -> bf16
    xT_kernel<<<dim3(PN / 32, PC / 64, PB), 256>>>(x, p_xT);

    // 3) qkt + fused row norms / max
    qk_gemm<<<dim3(1, PN / 128, PB), 256, QK_TOT>>>(p_xT, p_Wkb, p_qkt, bk, p_qn, p_mbits);

    // 4) E + partial sums   (<- profiled launch)
    scores_kernel<<<dim3(PN / 128, PN / 128, PB), 256, SC_TOT>>>(
        p_qkt, p_qn, p_mbits, p_E, p_lp);

    // 5) value
    value_gemm<<<dim3(PN / 128, PC / 128, PB), 128, VG_TOT>>>(p_Wvb, p_xT, p_v, bv);

    // 6) PV (+fused lred)
    pv_gemm<<<dim3(PN / 128, PC / 128, PB), 128, PV_TOT>>>(p_v, p_E, p_lp, gamma, x, out);
}